// round 16
// baseline (speedup 1.0000x reference)
#include <cuda_runtime.h>
#include <math.h>

#define HH 256
#define NDIM 64
#define LFULL 2048
#define M1024 1024
#define LHP 1026   // padded float2 stride per h

// ---- device scratch (no allocations allowed) ----
__device__ __align__(16) float2 g_kf[HH * LHP];
__device__ int g_flag[HH];   // zero-init; reset to 0 by consumer after acquire

// ================= f32x2 packed helpers =================
typedef unsigned long long ull;

__device__ __forceinline__ ull f2pack(float lo, float hi) {
    ull r; asm("mov.b64 %0, {%1,%2};" : "=l"(r) : "f"(lo), "f"(hi)); return r;
}
__device__ __forceinline__ void f2unpack(ull v, float& lo, float& hi) {
    asm("mov.b64 {%0,%1}, %2;" : "=f"(lo), "=f"(hi) : "l"(v));
}
__device__ __forceinline__ ull f2add(ull a, ull b) {
    ull r; asm("add.rn.f32x2 %0, %1, %2;" : "=l"(r) : "l"(a), "l"(b)); return r;
}
__device__ __forceinline__ ull f2mul(ull a, ull b) {
    ull r; asm("mul.rn.f32x2 %0, %1, %2;" : "=l"(r) : "l"(a), "l"(b)); return r;
}
__device__ __forceinline__ ull f2fma(ull a, ull b, ull c) {
    ull r; asm("fma.rn.f32x2 %0, %1, %2, %3;" : "=l"(r) : "l"(a), "l"(b), "l"(c)); return r;
}
__device__ __forceinline__ float frcp(float x) {
    float r; asm("rcp.approx.f32 %0, %1;" : "=f"(r) : "f"(x)); return r;
}
__device__ __forceinline__ float2 cmul(float2 a, float2 b) {
    return make_float2(a.x*b.x - a.y*b.y, a.x*b.y + a.y*b.x);
}

// union shared buffer: producer needs 5*64*16 = 5120 B;
// consumer needs (1024 + 256 + 1)*8 = 10248 B
#define SMEM_BYTES 10368

// ============================================================
// Single kernel, producers FIRST in bid order, 256 threads/block:
//   bids 0..511   : cauchy producers (h = bid>>1, half = bid&1)
//   bids 512..767 : ifft consumers (h = bid-512), spin on flag==2
// ============================================================
__global__ __launch_bounds__(256, 3)
void fused_overlap_kernel(const float* __restrict__ C, const float* __restrict__ B,
                          const float* __restrict__ P, const float* __restrict__ iwr,
                          const float* __restrict__ wim, const float* __restrict__ logdt,
                          float* __restrict__ out)
{
    __shared__ __align__(16) char smem_buf[SMEM_BYTES];
    const int tid = threadIdx.x;
    const float hw = (float)(3.1415926535897932384626433832795 / (double)LFULL);

    if (blockIdx.x < 512) {
        // ================= CAUCHY PRODUCER =================
        const int h    = blockIdx.x >> 1;
        const int half = blockIdx.x & 1;

        ulonglong2* sW  = (ulonglong2*)smem_buf;         // (cw,cw | dw,dw)
        ulonglong2* sV0 = sW  + NDIM;                    // (av,av | bv,bv)
        ulonglong2* sV1 = sV0 + NDIM;
        ulonglong2* sV2 = sV1 + NDIM;
        ulonglong2* sV3 = sV2 + NDIM;

        if (tid < NDIM) {
            int idx = h * NDIM + tid;
            float dt = expf(logdt[h]);
            float wr = -expf(iwr[idx]) * dt;
            float wi = wim[idx] * dt;

            float Cr = C[2*idx], Ci = C[2*idx + 1];
            float Br = B[2*idx], Bi = B[2*idx + 1];
            float Pr = P[2*idx], Pi = P[2*idx + 1];

            float v00r = (Br*Cr - Bi*Ci) * dt,  v00i = (Br*Ci + Bi*Cr) * dt;
            float v01r = (Br*Pr + Bi*Pi) * dt,  v01i = (Bi*Pr - Br*Pi) * dt; // B*conj(P)
            float v10r = (Pr*Cr - Pi*Ci) * dt,  v10i = (Pr*Ci + Pi*Cr) * dt;
            float v11r = (Pr*Pr + Pi*Pi) * dt;

            float cw = -2.0f * wr;
            float dw = wr*wr + wi*wi;

            float* q;
            q = (float*)&sW [tid]; q[0]=q[1]=cw; q[2]=q[3]=dw;
            q = (float*)&sV0[tid]; q[0]=q[1]=2.0f*v00r; q[2]=q[3]=-2.0f*(v00r*wr + v00i*wi);
            q = (float*)&sV1[tid]; q[0]=q[1]=2.0f*v01r; q[2]=q[3]=-2.0f*(v01r*wr + v01i*wi);
            q = (float*)&sV2[tid]; q[0]=q[1]=2.0f*v10r; q[2]=q[3]=-2.0f*(v10r*wr + v10i*wi);
            q = (float*)&sV3[tid]; q[0]=q[1]=2.0f*v11r; q[2]=q[3]=-2.0f*(v11r*wr);
        }
        __syncthreads();

        const int p  = half * 256 + tid;
        const int l0 = 2 * p;

        float y0 = 2.0f * tanf(hw * (float)l0);
        float y1 = 2.0f * tanf(hw * (float)(l0 + 1));

        const ull Y    = f2pack(y0, y1);
        const ull NY2  = f2pack(-y0*y0, -y1*y1);
        const ull ONE  = f2pack(1.0f, 1.0f);
        const ull NEG1 = f2pack(-1.0f, -1.0f);
        const ull HALF = f2pack(0.5f, 0.5f);

        ull A0=0,B0=0,C0=0,D0=0;
        ull A1=0,B1=0,C1=0,D1=0;
        ull A2=0,B2=0,C2=0,D2=0;
        ull A3=0,B3=0,C3=0,D3=0;

        #pragma unroll 8
        for (int n = 0; n < NDIM; n++) {
            ulonglong2 W = sW[n];
            ull er = f2add(W.y, NY2);                 // dw - y^2
            ull ei = f2mul(W.x, Y);                   // cw * y
            ull d2 = f2fma(ei, ei, f2mul(er, er));
            float lo, hi; f2unpack(d2, lo, hi);
            ull inv = f2pack(frcp(lo), frcp(hi));
            ull tr = f2mul(er, inv);
            ull ti = f2mul(ei, inv);

            ulonglong2 v;
            v = sV0[n];
            A0 = f2fma(v.x, tr, A0); B0 = f2fma(v.x, ti, B0);
            C0 = f2fma(v.y, tr, C0); D0 = f2fma(v.y, ti, D0);
            v = sV1[n];
            A1 = f2fma(v.x, tr, A1); B1 = f2fma(v.x, ti, B1);
            C1 = f2fma(v.y, tr, C1); D1 = f2fma(v.y, ti, D1);
            v = sV2[n];
            A2 = f2fma(v.x, tr, A2); B2 = f2fma(v.x, ti, B2);
            C2 = f2fma(v.y, tr, C2); D2 = f2fma(v.y, ti, D2);
            v = sV3[n];
            A3 = f2fma(v.x, tr, A3); B3 = f2fma(v.x, ti, B3);
            C3 = f2fma(v.y, tr, C3); D3 = f2fma(v.y, ti, D3);
        }

        // r = (C + y*B) + i*(y*A - D); Woodbury; *(1 + i y/2)
        ull r00r = f2fma(Y, B0, C0), r00i = f2fma(Y, A0, f2mul(NEG1, D0));
        ull r01r = f2fma(Y, B1, C1), r01i = f2fma(Y, A1, f2mul(NEG1, D1));
        ull r10r = f2fma(Y, B2, C2), r10i = f2fma(Y, A2, f2mul(NEG1, D2));
        ull r11r = f2fma(Y, B3, C3), r11i = f2fma(Y, A3, f2mul(NEG1, D3));

        ull d11r = f2add(ONE, r11r);
        ull d11i = r11i;
        ull den  = f2fma(d11i, d11i, f2mul(d11r, d11r));
        float dlo, dhi; f2unpack(den, dlo, dhi);
        ull dinv = f2pack(frcp(dlo), frcp(dhi));
        ull t2 = f2mul(r01i, r10i);
        ull nr = f2fma(r01r, r10r, f2mul(NEG1, t2));
        ull ni = f2fma(r01r, r10i, f2mul(r01i, r10r));
        ull qr = f2mul(f2fma(ni, d11i, f2mul(nr, d11r)), dinv);
        ull qi = f2mul(f2fma(ni, d11r, f2mul(NEG1, f2mul(nr, d11i))), dinv);
        ull kr = f2fma(NEG1, qr, r00r);
        ull ki = f2fma(NEG1, qi, r00i);

        ull Y2  = f2mul(Y, HALF);
        ull kfr = f2fma(NEG1, f2mul(Y2, ki), kr);
        ull kfi = f2fma(Y2, kr, ki);

        float kr0, kr1, ki0, ki1;
        f2unpack(kfr, kr0, kr1);
        f2unpack(kfi, ki0, ki1);
        *(float4*)&g_kf[h * LHP + l0] = make_float4(kr0, ki0, kr1, ki1);

        // release: data visible before flag increment
        __threadfence();
        __syncthreads();
        if (tid == 0) atomicAdd(&g_flag[h], 1);
        return;
    }

    // ================= IFFT CONSUMER (256 threads) =================
    const int h = blockIdx.x - 512;
    float2* X      = (float2*)smem_buf;            // [1024]
    float2* tw     = X + M1024;                    // [256]
    float2* s1024p = tw + 256;                     // [1]

    // twiddle table: tw[m] = exp(+i*2*pi*m/1024)
    {
        float s, c;
        __sincosf((float)(6.283185307179586 / 1024.0) * (float)tid, &s, &c);
        tw[tid] = make_float2(c, s);
    }

    // warp 0: k_f at l=1024 (independent of g_kf -> done before the wait)
    if (tid < 32) {
        const float y = 2.0f * tanf(hw * 1024.0f);
        const float ny2 = -y * y;
        float dt = expf(logdt[h]);

        float A0=0.f,B0=0.f,C0=0.f,D0=0.f;
        float A1=0.f,B1=0.f,C1=0.f,D1=0.f;
        float A2=0.f,B2=0.f,C2=0.f,D2=0.f;
        float A3=0.f,B3=0.f,C3=0.f,D3=0.f;

        #pragma unroll
        for (int k = 0; k < 2; k++) {
            int n = tid + k * 32;
            int idx = h * NDIM + n;
            float wr = -expf(iwr[idx]) * dt;
            float wi = wim[idx] * dt;
            float Cr = C[2*idx], Ci = C[2*idx + 1];
            float Br = B[2*idx], Bi = B[2*idx + 1];
            float Pr = P[2*idx], Pi = P[2*idx + 1];

            float v00r = (Br*Cr - Bi*Ci) * dt,  v00i = (Br*Ci + Bi*Cr) * dt;
            float v01r = (Br*Pr + Bi*Pi) * dt,  v01i = (Bi*Pr - Br*Pi) * dt;
            float v10r = (Pr*Cr - Pi*Ci) * dt,  v10i = (Pr*Ci + Pi*Cr) * dt;
            float v11r = (Pr*Pr + Pi*Pi) * dt;

            float av0 = 2.0f*v00r, bv0 = -2.0f*(v00r*wr + v00i*wi);
            float av1 = 2.0f*v01r, bv1 = -2.0f*(v01r*wr + v01i*wi);
            float av2 = 2.0f*v10r, bv2 = -2.0f*(v10r*wr + v10i*wi);
            float av3 = 2.0f*v11r, bv3 = -2.0f*(v11r*wr);

            float er = (wr*wr + wi*wi) + ny2;
            float ei = (-2.0f*wr) * y;
            float inv = frcp(er*er + ei*ei);
            float tr = er * inv, ti = ei * inv;

            A0 += av0*tr; B0 += av0*ti; C0 += bv0*tr; D0 += bv0*ti;
            A1 += av1*tr; B1 += av1*ti; C1 += bv1*tr; D1 += bv1*ti;
            A2 += av2*tr; B2 += av2*ti; C2 += bv2*tr; D2 += bv2*ti;
            A3 += av3*tr; B3 += av3*ti; C3 += bv3*tr; D3 += bv3*ti;
        }
        #pragma unroll
        for (int off = 16; off > 0; off >>= 1) {
            A0 += __shfl_xor_sync(0xffffffffu, A0, off);
            B0 += __shfl_xor_sync(0xffffffffu, B0, off);
            C0 += __shfl_xor_sync(0xffffffffu, C0, off);
            D0 += __shfl_xor_sync(0xffffffffu, D0, off);
            A1 += __shfl_xor_sync(0xffffffffu, A1, off);
            B1 += __shfl_xor_sync(0xffffffffu, B1, off);
            C1 += __shfl_xor_sync(0xffffffffu, C1, off);
            D1 += __shfl_xor_sync(0xffffffffu, D1, off);
            A2 += __shfl_xor_sync(0xffffffffu, A2, off);
            B2 += __shfl_xor_sync(0xffffffffu, B2, off);
            C2 += __shfl_xor_sync(0xffffffffu, C2, off);
            D2 += __shfl_xor_sync(0xffffffffu, D2, off);
            A3 += __shfl_xor_sync(0xffffffffu, A3, off);
            B3 += __shfl_xor_sync(0xffffffffu, B3, off);
            C3 += __shfl_xor_sync(0xffffffffu, C3, off);
            D3 += __shfl_xor_sync(0xffffffffu, D3, off);
        }
        if (tid == 0) {
            float r00r = C0 + y*B0, r00i = y*A0 - D0;
            float r01r = C1 + y*B1, r01i = y*A1 - D1;
            float r10r = C2 + y*B2, r10i = y*A2 - D2;
            float r11r = C3 + y*B3, r11i = y*A3 - D3;
            float d11r = 1.0f + r11r, d11i = r11i;
            float dinv = frcp(d11r*d11r + d11i*d11i);
            float nr = r01r*r10r - r01i*r10i;
            float ni = r01r*r10i + r01i*r10r;
            float qr = (nr*d11r + ni*d11i) * dinv;
            float qi = (ni*d11r - nr*d11i) * dinv;
            float kr = r00r - qr, ki = r00i - qi;
            float y2 = 0.5f * y;
            s1024p[0] = make_float2(kr - y2*ki, ki + y2*kr);
        }
    }

    // ---- acquire: wait for this h's 2 producer blocks ----
    if (tid == 0) {
        while (atomicAdd(&g_flag[h], 0) < 2) __nanosleep(256);
        g_flag[h] = 0;   // reset for next graph replay (kernel boundary serializes)
    }
    __syncthreads();

    const float2* kf = &g_kf[h * LHP];

    // ---- build Z (real-packed half-size spectrum), scale folded in ----
    // Z[m] = (E + i*O)/1024
    const float sc = 1.0f / 1024.0f;
    #pragma unroll
    for (int m = tid; m < M1024; m += 256) {
        float2 Ka = __ldcg(kf + m);
        float2 Kb = (m == 0) ? s1024p[0] : __ldcg(kf + (M1024 - m));
        float Er = 0.5f * (Ka.x + Kb.x);
        float Ei = 0.5f * (Ka.y - Kb.y);
        float Fr = 0.5f * (Ka.x - Kb.x);
        float Fi = 0.5f * (Ka.y + Kb.y);
        float s, c;
        __sincosf((float)(3.141592653589793 / 1024.0) * (float)m, &s, &c);
        float Or = c*Fr - s*Fi;
        float Oi = c*Fi + s*Fr;
        X[m] = make_float2((Er - Oi) * sc, (Ei + Or) * sc);
    }
    __syncthreads();

    // ---- base-4 digit reversal (10 bits) ----
    #pragma unroll
    for (int i = tid; i < M1024; i += 256) {
        unsigned r = __brev((unsigned)i) >> 22;
        r = ((r & 0x155u) << 1) | ((r >> 1) & 0x155u);
        if ((int)r > i) { float2 tswap = X[i]; X[i] = X[r]; X[r] = tswap; }
    }
    __syncthreads();

    // ---- stage 0: radix-4 on consecutive quads, float4 access ----
    {
        float4 lo4 = *(const float4*)&X[4*tid];
        float4 hi4 = *(const float4*)&X[4*tid + 2];
        float2 a = make_float2(lo4.x, lo4.y), b = make_float2(lo4.z, lo4.w);
        float2 c = make_float2(hi4.x, hi4.y), d = make_float2(hi4.z, hi4.w);
        float2 apc = make_float2(a.x+c.x, a.y+c.y), amc = make_float2(a.x-c.x, a.y-c.y);
        float2 bpd = make_float2(b.x+d.x, b.y+d.y), bmd = make_float2(b.x-d.x, b.y-d.y);
        float2 y0 = make_float2(apc.x+bpd.x, apc.y+bpd.y);
        float2 y1 = make_float2(amc.x-bmd.y, amc.y+bmd.x);
        float2 y2 = make_float2(apc.x-bpd.x, apc.y-bpd.y);
        float2 y3 = make_float2(amc.x+bmd.y, amc.y-bmd.x);
        *(float4*)&X[4*tid]     = make_float4(y0.x, y0.y, y1.x, y1.y);
        *(float4*)&X[4*tid + 2] = make_float4(y2.x, y2.y, y3.x, y3.y);
    }
    __syncthreads();

    // ---- stages 1..4 (inverse: +i); one butterfly per thread ----
    #pragma unroll
    for (int st = 1; st < 5; st++) {
        int q = 1 << (2*st);
        int j = tid & (q - 1);
        int i0 = ((tid >> (2*st)) << (2*st + 2)) + j;
        float2 w1 = tw[j << (2*(4 - st))];
        float2 w2 = cmul(w1, w1);
        float2 w3 = cmul(w2, w1);

        float2 a = X[i0];
        float2 b = cmul(X[i0 + q],   w1);
        float2 c = cmul(X[i0 + 2*q], w2);
        float2 d = cmul(X[i0 + 3*q], w3);
        float2 apc = make_float2(a.x+c.x, a.y+c.y), amc = make_float2(a.x-c.x, a.y-c.y);
        float2 bpd = make_float2(b.x+d.x, b.y+d.y), bmd = make_float2(b.x-d.x, b.y-d.y);
        X[i0]       = make_float2(apc.x+bpd.x, apc.y+bpd.y);
        X[i0 + q]   = make_float2(amc.x-bmd.y, amc.y+bmd.x);
        X[i0 + 2*q] = make_float2(apc.x-bpd.x, apc.y-bpd.y);
        X[i0 + 3*q] = make_float2(amc.x+bmd.y, amc.y-bmd.x);
        __syncthreads();
    }

    // ---- unpack to real output: x[2t]=Re z[t], x[2t+1]=Im z[t] ----
    float2* out2 = (float2*)(out + h * LFULL);
    #pragma unroll
    for (int m = tid; m < M1024; m += 256) {
        out2[m] = X[m];
    }
}

// ============================================================
extern "C" void kernel_launch(void* const* d_in, const int* in_sizes, int n_in,
                              void* d_out, int out_size)
{
    const float* C     = (const float*)d_in[0];   // (1,256,64,2)
    const float* B     = (const float*)d_in[1];   // (1,256,64,2)
    const float* P     = (const float*)d_in[2];   // (1,256,64,2)
    const float* iwr   = (const float*)d_in[3];   // (256,64)
    const float* wim   = (const float*)d_in[4];   // (256,64)
    const float* logdt = (const float*)d_in[5];   // (256,)
    (void)in_sizes; (void)n_in; (void)out_size;

    // bids 0..511: cauchy producers (scheduled first);
    // bids 512..767: ifft consumers (256 threads -> fast FFT tail)
    fused_overlap_kernel<<<768, 256>>>(C, B, P, iwr, wim, logdt, (float*)d_out);
}

// round 17
// speedup vs baseline: 1.1338x; 1.1338x over previous
#include <cuda_runtime.h>
#include <math.h>

#define HH 256
#define NDIM 64
#define LFULL 2048
#define M1024 1024
#define NT 512

// ================= f32x2 packed helpers =================
typedef unsigned long long ull;

__device__ __forceinline__ ull f2pack(float lo, float hi) {
    ull r; asm("mov.b64 %0, {%1,%2};" : "=l"(r) : "f"(lo), "f"(hi)); return r;
}
__device__ __forceinline__ void f2unpack(ull v, float& lo, float& hi) {
    asm("mov.b64 {%0,%1}, %2;" : "=f"(lo), "=f"(hi) : "l"(v));
}
__device__ __forceinline__ ull f2add(ull a, ull b) {
    ull r; asm("add.rn.f32x2 %0, %1, %2;" : "=l"(r) : "l"(a), "l"(b)); return r;
}
__device__ __forceinline__ ull f2mul(ull a, ull b) {
    ull r; asm("mul.rn.f32x2 %0, %1, %2;" : "=l"(r) : "l"(a), "l"(b)); return r;
}
__device__ __forceinline__ ull f2fma(ull a, ull b, ull c) {
    ull r; asm("fma.rn.f32x2 %0, %1, %2, %3;" : "=l"(r) : "l"(a), "l"(b), "l"(c)); return r;
}
__device__ __forceinline__ float frcp(float x) {
    float r; asm("rcp.approx.f32 %0, %1;" : "=f"(r) : "f"(x)); return r;
}
__device__ __forceinline__ float2 cmul(float2 a, float2 b) {
    return make_float2(a.x*b.x - a.y*b.y, a.x*b.y + a.y*b.x);
}

// ============================================================
// Fully fused: prep + Cauchy/Woodbury (f32x2, 1 pack/thread)
// + real-packed half-size radix-4 inverse FFT. One block per h.
// This is the best-measured configuration (R6: 28.99 us).
// ============================================================
__global__ __launch_bounds__(NT)
void fused_kernel(const float* __restrict__ C, const float* __restrict__ B,
                  const float* __restrict__ P, const float* __restrict__ iwr,
                  const float* __restrict__ wim, const float* __restrict__ logdt,
                  float* __restrict__ out)
{
    __shared__ ulonglong2 sW [NDIM];   // (cw,cw | dw,dw)
    __shared__ ulonglong2 sV0[NDIM];   // (av,av | bv,bv) for v00
    __shared__ ulonglong2 sV1[NDIM];   // v01
    __shared__ ulonglong2 sV2[NDIM];   // v10
    __shared__ ulonglong2 sV3[NDIM];   // v11
    __shared__ float2 skf[1026];       // k_f[0..1024]
    __shared__ __align__(16) float2 X[M1024];  // FFT workspace
    __shared__ float2 tw[256];         // tw[m] = exp(+i*2*pi*m/1024)

    const int h   = blockIdx.x;
    const int tid = threadIdx.x;

    // ---------- phase 0: parameter prep ----------
    if (tid < NDIM) {
        int idx = h * NDIM + tid;
        float dt = expf(logdt[h]);
        float wr = -expf(iwr[idx]) * dt;
        float wi = wim[idx] * dt;

        float Cr = C[2*idx], Ci = C[2*idx + 1];
        float Br = B[2*idx], Bi = B[2*idx + 1];
        float Pr = P[2*idx], Pi = P[2*idx + 1];

        float v00r = (Br*Cr - Bi*Ci) * dt,  v00i = (Br*Ci + Bi*Cr) * dt;
        float v01r = (Br*Pr + Bi*Pi) * dt,  v01i = (Bi*Pr - Br*Pi) * dt;  // B*conj(P)
        float v10r = (Pr*Cr - Pi*Ci) * dt,  v10i = (Pr*Ci + Pi*Cr) * dt;
        float v11r = (Pr*Pr + Pi*Pi) * dt;

        float cw = -2.0f * wr;
        float dw = wr*wr + wi*wi;

        float* q;
        q = (float*)&sW [tid]; q[0]=q[1]=cw; q[2]=q[3]=dw;
        q = (float*)&sV0[tid]; q[0]=q[1]=2.0f*v00r; q[2]=q[3]=-2.0f*(v00r*wr + v00i*wi);
        q = (float*)&sV1[tid]; q[0]=q[1]=2.0f*v01r; q[2]=q[3]=-2.0f*(v01r*wr + v01i*wi);
        q = (float*)&sV2[tid]; q[0]=q[1]=2.0f*v10r; q[2]=q[3]=-2.0f*(v10r*wr + v10i*wi);
        q = (float*)&sV3[tid]; q[0]=q[1]=2.0f*v11r; q[2]=q[3]=-2.0f*(v11r*wr);
    }
    // twiddle table fill
    if (tid >= 256 && tid < 512) {
        int m = tid - 256;
        float s, c;
        sincosf((float)(6.283185307179586 / 1024.0) * (float)m, &s, &c);
        tw[m] = make_float2(c, s);
    }
    __syncthreads();

    const float hw = (float)(3.1415926535897932384626433832795 / (double)LFULL);

    // ---------- phase 1a: one pair-pack per thread (pairs 0..511) ----------
    {
        const int l0 = 2 * tid;

        float y0 = 2.0f * tanf(hw * (float)l0);
        float y1 = 2.0f * tanf(hw * (float)(l0 + 1));

        const ull Y    = f2pack(y0, y1);
        const ull NY2  = f2pack(-y0*y0, -y1*y1);
        const ull ONE  = f2pack(1.0f, 1.0f);
        const ull NEG1 = f2pack(-1.0f, -1.0f);
        const ull HALF = f2pack(0.5f, 0.5f);

        ull A0=0,B0=0,C0=0,D0=0;
        ull A1=0,B1=0,C1=0,D1=0;
        ull A2=0,B2=0,C2=0,D2=0;
        ull A3=0,B3=0,C3=0,D3=0;

        #pragma unroll 8
        for (int n = 0; n < NDIM; n++) {
            ulonglong2 W = sW[n];
            ull er = f2add(W.y, NY2);                 // dw - y^2
            ull ei = f2mul(W.x, Y);                   // cw * y
            ull d2 = f2fma(ei, ei, f2mul(er, er));
            float lo, hi; f2unpack(d2, lo, hi);
            ull inv = f2pack(frcp(lo), frcp(hi));
            ull tr = f2mul(er, inv);
            ull ti = f2mul(ei, inv);

            ulonglong2 v;
            v = sV0[n];
            A0 = f2fma(v.x, tr, A0); B0 = f2fma(v.x, ti, B0);
            C0 = f2fma(v.y, tr, C0); D0 = f2fma(v.y, ti, D0);
            v = sV1[n];
            A1 = f2fma(v.x, tr, A1); B1 = f2fma(v.x, ti, B1);
            C1 = f2fma(v.y, tr, C1); D1 = f2fma(v.y, ti, D1);
            v = sV2[n];
            A2 = f2fma(v.x, tr, A2); B2 = f2fma(v.x, ti, B2);
            C2 = f2fma(v.y, tr, C2); D2 = f2fma(v.y, ti, D2);
            v = sV3[n];
            A3 = f2fma(v.x, tr, A3); B3 = f2fma(v.x, ti, B3);
            C3 = f2fma(v.y, tr, C3); D3 = f2fma(v.y, ti, D3);
        }

        // r = (C + y*B) + i*(y*A - D)
        ull r00r = f2fma(Y, B0, C0), r00i = f2fma(Y, A0, f2mul(NEG1, D0));
        ull r01r = f2fma(Y, B1, C1), r01i = f2fma(Y, A1, f2mul(NEG1, D1));
        ull r10r = f2fma(Y, B2, C2), r10i = f2fma(Y, A2, f2mul(NEG1, D2));
        ull r11r = f2fma(Y, B3, C3), r11i = f2fma(Y, A3, f2mul(NEG1, D3));

        // Woodbury: k = r00 - r01*r10/(1+r11)
        ull d11r = f2add(ONE, r11r);
        ull d11i = r11i;
        ull den  = f2fma(d11i, d11i, f2mul(d11r, d11r));
        float dlo, dhi; f2unpack(den, dlo, dhi);
        ull dinv = f2pack(frcp(dlo), frcp(dhi));
        ull t2 = f2mul(r01i, r10i);
        ull nr = f2fma(r01r, r10r, f2mul(NEG1, t2));
        ull ni = f2fma(r01r, r10i, f2mul(r01i, r10r));
        ull qr = f2mul(f2fma(ni, d11i, f2mul(nr, d11r)), dinv);
        ull qi = f2mul(f2fma(ni, d11r, f2mul(NEG1, f2mul(nr, d11i))), dinv);
        ull kr = f2fma(NEG1, qr, r00r);
        ull ki = f2fma(NEG1, qi, r00i);

        // * (1 + i*y/2)
        ull Y2  = f2mul(Y, HALF);
        ull kfr = f2fma(NEG1, f2mul(Y2, ki), kr);
        ull kfi = f2fma(Y2, kr, ki);

        float kr0, kr1, ki0, ki1;
        f2unpack(kfr, kr0, kr1);
        f2unpack(kfi, ki0, ki1);

        skf[l0]     = make_float2(kr0, ki0);
        skf[l0 + 1] = make_float2(kr1, ki1);
    }

    // ---------- phase 1b: pair 512 (l = 1024) by warp 0 cooperatively ----------
    if (tid < 32) {
        const float y = 2.0f * tanf(hw * 1024.0f);
        const float ny2 = -y * y;
        float A0=0.f,B0=0.f,C0=0.f,D0=0.f;
        float A1=0.f,B1=0.f,C1=0.f,D1=0.f;
        float A2=0.f,B2=0.f,C2=0.f,D2=0.f;
        float A3=0.f,B3=0.f,C3=0.f,D3=0.f;

        #pragma unroll
        for (int k = 0; k < 2; k++) {
            int n = tid + k * 32;
            const float* W = (const float*)&sW[n];
            float er = W[2] + ny2;        // dw - y^2
            float ei = W[0] * y;          // cw * y
            float inv = frcp(er*er + ei*ei);
            float tr = er * inv, ti = ei * inv;
            const float* v;
            v = (const float*)&sV0[n];
            A0 += v[0]*tr; B0 += v[0]*ti; C0 += v[2]*tr; D0 += v[2]*ti;
            v = (const float*)&sV1[n];
            A1 += v[0]*tr; B1 += v[0]*ti; C1 += v[2]*tr; D1 += v[2]*ti;
            v = (const float*)&sV2[n];
            A2 += v[0]*tr; B2 += v[0]*ti; C2 += v[2]*tr; D2 += v[2]*ti;
            v = (const float*)&sV3[n];
            A3 += v[0]*tr; B3 += v[0]*ti; C3 += v[2]*tr; D3 += v[2]*ti;
        }
        #pragma unroll
        for (int off = 16; off > 0; off >>= 1) {
            A0 += __shfl_xor_sync(0xffffffffu, A0, off);
            B0 += __shfl_xor_sync(0xffffffffu, B0, off);
            C0 += __shfl_xor_sync(0xffffffffu, C0, off);
            D0 += __shfl_xor_sync(0xffffffffu, D0, off);
            A1 += __shfl_xor_sync(0xffffffffu, A1, off);
            B1 += __shfl_xor_sync(0xffffffffu, B1, off);
            C1 += __shfl_xor_sync(0xffffffffu, C1, off);
            D1 += __shfl_xor_sync(0xffffffffu, D1, off);
            A2 += __shfl_xor_sync(0xffffffffu, A2, off);
            B2 += __shfl_xor_sync(0xffffffffu, B2, off);
            C2 += __shfl_xor_sync(0xffffffffu, C2, off);
            D2 += __shfl_xor_sync(0xffffffffu, D2, off);
            A3 += __shfl_xor_sync(0xffffffffu, A3, off);
            B3 += __shfl_xor_sync(0xffffffffu, B3, off);
            C3 += __shfl_xor_sync(0xffffffffu, C3, off);
            D3 += __shfl_xor_sync(0xffffffffu, D3, off);
        }
        if (tid == 0) {
            float r00r = C0 + y*B0, r00i = y*A0 - D0;
            float r01r = C1 + y*B1, r01i = y*A1 - D1;
            float r10r = C2 + y*B2, r10i = y*A2 - D2;
            float r11r = C3 + y*B3, r11i = y*A3 - D3;
            float d11r = 1.0f + r11r, d11i = r11i;
            float dinv = frcp(d11r*d11r + d11i*d11i);
            float nr = r01r*r10r - r01i*r10i;
            float ni = r01r*r10i + r01i*r10r;
            float qr = (nr*d11r + ni*d11i) * dinv;
            float qi = (ni*d11r - nr*d11i) * dinv;
            float kr = r00r - qr, ki = r00i - qi;
            float y2 = 0.5f * y;
            skf[1024] = make_float2(kr - y2*ki, ki + y2*kr);
        }
    }
    __syncthreads();

    // ---------- phase 2: build Z (real-packed half-size spectrum) ----------
    // Z[m] = E + i*O; E=(K[m]+conj(K[M-m]))/2, O=e^{+i*pi*m/1024}*(K[m]-conj(K[M-m]))/2
    #pragma unroll
    for (int m = tid; m < M1024; m += NT) {
        float2 Ka = skf[m];
        float2 Kb = skf[M1024 - m];
        float Er = 0.5f * (Ka.x + Kb.x);
        float Ei = 0.5f * (Ka.y - Kb.y);
        float Fr = 0.5f * (Ka.x - Kb.x);
        float Fi = 0.5f * (Ka.y + Kb.y);
        float s, c;
        sincosf((float)(3.141592653589793 / 1024.0) * (float)m, &s, &c);
        float Or = c*Fr - s*Fi;
        float Oi = c*Fi + s*Fr;
        X[m] = make_float2(Er - Oi, Ei + Or);
    }
    __syncthreads();

    // ---------- phase 3: base-4 digit reversal (10 bits) ----------
    #pragma unroll
    for (int i = tid; i < M1024; i += NT) {
        unsigned r = __brev((unsigned)i) >> 22;
        r = ((r & 0x155u) << 1) | ((r >> 1) & 0x155u);
        if ((int)r > i) { float2 tswap = X[i]; X[i] = X[r]; X[r] = tswap; }
    }
    __syncthreads();

    // ---------- phase 4: 5 radix-4 DIT stages (inverse: +i); 256 butterflies ----------
    if (tid < 256) {
        float4 lo4 = *(const float4*)&X[4*tid];
        float4 hi4 = *(const float4*)&X[4*tid + 2];
        float2 a = make_float2(lo4.x, lo4.y), b = make_float2(lo4.z, lo4.w);
        float2 c = make_float2(hi4.x, hi4.y), d = make_float2(hi4.z, hi4.w);
        float2 apc = make_float2(a.x+c.x, a.y+c.y), amc = make_float2(a.x-c.x, a.y-c.y);
        float2 bpd = make_float2(b.x+d.x, b.y+d.y), bmd = make_float2(b.x-d.x, b.y-d.y);
        float2 y0 = make_float2(apc.x+bpd.x, apc.y+bpd.y);
        float2 y1 = make_float2(amc.x-bmd.y, amc.y+bmd.x);
        float2 y2 = make_float2(apc.x-bpd.x, apc.y-bpd.y);
        float2 y3 = make_float2(amc.x+bmd.y, amc.y-bmd.x);
        *(float4*)&X[4*tid]     = make_float4(y0.x, y0.y, y1.x, y1.y);
        *(float4*)&X[4*tid + 2] = make_float4(y2.x, y2.y, y3.x, y3.y);
    }
    __syncthreads();

    #pragma unroll
    for (int st = 1; st < 5; st++) {
        if (tid < 256) {
            int q = 1 << (2*st);
            int j = tid & (q - 1);
            int i0 = ((tid >> (2*st)) << (2*st + 2)) + j;
            float2 w1 = tw[j << (2*(4 - st))];
            float2 w2 = cmul(w1, w1);
            float2 w3 = cmul(w2, w1);

            float2 a = X[i0];
            float2 b = cmul(X[i0 + q],   w1);
            float2 c = cmul(X[i0 + 2*q], w2);
            float2 d = cmul(X[i0 + 3*q], w3);
            float2 apc = make_float2(a.x+c.x, a.y+c.y), amc = make_float2(a.x-c.x, a.y-c.y);
            float2 bpd = make_float2(b.x+d.x, b.y+d.y), bmd = make_float2(b.x-d.x, b.y-d.y);
            X[i0]       = make_float2(apc.x+bpd.x, apc.y+bpd.y);
            X[i0 + q]   = make_float2(amc.x-bmd.y, amc.y+bmd.x);
            X[i0 + 2*q] = make_float2(apc.x-bpd.x, apc.y-bpd.y);
            X[i0 + 3*q] = make_float2(amc.x+bmd.y, amc.y-bmd.x);
        }
        __syncthreads();
    }

    // ---------- phase 5: unpack to real output ----------
    const float sc = 1.0f / 1024.0f;
    float2* out2 = (float2*)(out + h * LFULL);
    #pragma unroll
    for (int t = tid; t < M1024; t += NT) {
        float2 z = X[t];
        out2[t] = make_float2(z.x * sc, z.y * sc);
    }
}

// ============================================================
extern "C" void kernel_launch(void* const* d_in, const int* in_sizes, int n_in,
                              void* d_out, int out_size)
{
    const float* C     = (const float*)d_in[0];   // (1,256,64,2)
    const float* B     = (const float*)d_in[1];   // (1,256,64,2)
    const float* P     = (const float*)d_in[2];   // (1,256,64,2)
    const float* iwr   = (const float*)d_in[3];   // (256,64)
    const float* wim   = (const float*)d_in[4];   // (256,64)
    const float* logdt = (const float*)d_in[5];   // (256,)
    (void)in_sizes; (void)n_in; (void)out_size;

    fused_kernel<<<HH, NT>>>(C, B, P, iwr, wim, logdt, (float*)d_out);
}